// round 8
// baseline (speedup 1.0000x reference)
#include <cuda_runtime.h>
#include <cstdint>

// GatherBlock: out[m, :, :, :] = x[b[m], :, yb[m]*16 : yb[m]*16+16, xb[m]*16 : xb[m]*16+16]
// x: (8, 64, 256, 256) fp32, indices: (1024, 3) int32, out: (1024, 64, 16, 16) fp32.
//
// R8: raise memory-level parallelism per SM. All pipes sat at ~50% (latency/
// queue equilibrium, not a bandwidth wall), so throughput = bytes-in-flight /
// latency. Switch gather CTAs to 128 threads x 8 front-batched LDG.128
// (~192KB in flight/SM vs 128KB before). Keep: counting-sort tile-ordered
// schedule (free, ~0.2us), __ldcg read-once loads, __stcs streaming stores.

static constexpr int C = 64;
static constexpr int H = 256;
static constexpr int W = 256;
static constexpr int BH = 16;
static constexpr int BW = 16;
static constexpr int CHW = C * H * W;      // 4194304
static constexpr int HW = H * W;           // 65536
static constexpr int VEC_PER_M = C * BH * BW / 4;     // 4096 float4 per output block
static constexpr int SPLIT = 4;                       // CTAs per m
static constexpr int VEC_PER_CTA = VEC_PER_M / SPLIT; // 1024 float4 per CTA
static constexpr int M_MAX = 1024;
static constexpr int BINS = 2048;                     // 8*16*16 tile ids
static constexpr int TPB = 128;                       // threads per gather CTA
static constexpr int LPT = VEC_PER_CTA / TPB;         // 8 float4 per thread

__device__ int g_perm[M_MAX];

__global__ __launch_bounds__(M_MAX, 1)
void sort_indices_kernel(const int* __restrict__ idx, int M)
{
    __shared__ unsigned hist[BINS];
    __shared__ unsigned warpsum[32];

    const int t = threadIdx.x;
    const int lane = t & 31;
    const int wid = t >> 5;

    hist[2 * t]     = 0;
    hist[2 * t + 1] = 0;
    __syncthreads();

    int key = 0;
    if (t < M) {
        const int b  = idx[3 * t + 0];
        const int yb = idx[3 * t + 1];
        const int xb = idx[3 * t + 2];
        key = (b << 8) | (yb << 4) | xb;   // 11 bits
        atomicAdd(&hist[key], 1u);
    }
    __syncthreads();

    const unsigned a = hist[2 * t];
    const unsigned bcnt = hist[2 * t + 1];
    const unsigned s = a + bcnt;

    unsigned incl = s;
#pragma unroll
    for (int d = 1; d < 32; d <<= 1) {
        const unsigned n = __shfl_up_sync(0xFFFFFFFFu, incl, d);
        if (lane >= d) incl += n;
    }
    const unsigned thr_excl = incl - s;
    if (lane == 31) warpsum[wid] = incl;
    __syncthreads();

    if (wid == 0) {
        unsigned v = warpsum[lane];
        unsigned pv = v;
#pragma unroll
        for (int d = 1; d < 32; d <<= 1) {
            const unsigned n = __shfl_up_sync(0xFFFFFFFFu, pv, d);
            if (lane >= d) pv += n;
        }
        warpsum[lane] = pv - v;
    }
    __syncthreads();

    const unsigned base = warpsum[wid] + thr_excl;
    hist[2 * t]     = base;
    hist[2 * t + 1] = base + a;
    __syncthreads();

    if (t < M) {
        const unsigned pos = atomicAdd(&hist[key], 1u);
        g_perm[pos] = t;
    }
}

__global__ __launch_bounds__(TPB)
void gather_block_kernel(const float* __restrict__ x,
                         const int* __restrict__ idx,
                         float4* __restrict__ out)
{
    const int m = g_perm[blockIdx.x >> 2];  // tile-address-sorted order
    const int q = blockIdx.x & 3;           // which quarter of the block

    const int b  = idx[3 * m + 0];
    const int yb = idx[3 * m + 1];
    const int xb = idx[3 * m + 2];

    // base of the gathered tile: x[b, 0, yb*16, xb*16]
    const float* src = x + (size_t)b * CHW + (size_t)(yb * BH) * W + (size_t)(xb * BW);
    float4* dst = out + (size_t)m * VEC_PER_M;

    const int t = threadIdx.x;
    const int v0 = q * VEC_PER_CTA + t;     // starting float4 index within the block

    // v in [0, 4096): c = v>>6, row i = (v>>2)&15, j-vector = v&3.
    // Front-batch all 8 loads (max in-flight), then stream-store.
    float4 r[LPT];
#pragma unroll
    for (int k = 0; k < LPT; k++) {
        const int v = v0 + k * TPB;
        const int c = v >> 6;
        const int i = (v >> 2) & 15;
        const int j = v & 3;
        const float4* s = reinterpret_cast<const float4*>(
            src + (size_t)c * HW + (size_t)i * W) + j;
        r[k] = __ldcg(s);
    }
#pragma unroll
    for (int k = 0; k < LPT; k++) {
        __stcs(dst + v0 + k * TPB, r[k]);
    }
}

extern "C" void kernel_launch(void* const* d_in, const int* in_sizes, int n_in,
                              void* d_out, int out_size)
{
    const float* x  = (const float*)d_in[0];
    const int* idx  = (const int*)d_in[1];
    float4* out     = (float4*)d_out;

    const int M = in_sizes[1] / 3;  // 1024
    sort_indices_kernel<<<1, M_MAX>>>(idx, M);
    gather_block_kernel<<<M * SPLIT, TPB>>>(x, idx, out);
}